// round 12
// baseline (speedup 1.0000x reference)
#include <cuda_runtime.h>
#include <cuda_fp16.h>

// 5-level db4 DWT, symmetric extension. fp16 smem cascade (fp32 scalar FMA),
// 4 outputs/thread from 2 conflict-free aligned LDS.128 (R5 hot loop).
// ENTIRE cascade specialized at compile time on row&3: all shifts, smem
// offsets, trip counts and bounds constant-folded; loops fully unrolled.

#define NROWS 4096
#define NT    256

#define L0 4096
#define L1 2051
#define L2 1029
#define L3 518
#define L4 262
#define L5 134

#define O_APPROX 0
#define O_D5 (NROWS * L5)
#define O_D4 (O_D5 + NROWS * L5)
#define O_D3 (O_D4 + NROWS * L4)
#define O_D2 (O_D3 + NROWS * L3)
#define O_D1 (O_D2 + NROWS * L2)

// Reversed filters: y[j] = sum_r RF[r] * ext[2j + r]
#define RLO0  0.23037781330885523f
#define RLO1  0.7148465705525415f
#define RLO2  0.6308807679295904f
#define RLO3 -0.02798376941698385f
#define RLO4 -0.18703481171888114f
#define RLO5  0.030841381835986965f
#define RLO6  0.032883011666982945f
#define RLO7 -0.010597401784997278f

#define RHI0 -0.010597401784997278f
#define RHI1 -0.032883011666982945f
#define RHI2  0.030841381835986965f
#define RHI3  0.18703481171888114f
#define RHI4 -0.02798376941698385f
#define RHI5 -0.6308807679295904f
#define RHI6  0.7148465705525415f
#define RHI7 -0.23037781330885523f

__device__ __forceinline__ void taps8(const float* w, float& l, float& h) {
    l = RLO0 * w[0];
    l = fmaf(RLO1, w[1], l); l = fmaf(RLO2, w[2], l);
    l = fmaf(RLO3, w[3], l); l = fmaf(RLO4, w[4], l);
    l = fmaf(RLO5, w[5], l); l = fmaf(RLO6, w[6], l);
    l = fmaf(RLO7, w[7], l);
    h = RHI0 * w[0];
    h = fmaf(RHI1, w[1], h); h = fmaf(RHI2, w[2], h);
    h = fmaf(RHI3, w[3], h); h = fmaf(RHI4, w[4], h);
    h = fmaf(RHI5, w[5], h); h = fmaf(RHI6, w[6], h);
    h = fmaf(RHI7, w[7], h);
}

// One level, fully compile-time shapes. q: fp16 ext buffer (ext[i] = q[C+i]),
// input length N, M=(N+7)/2 outputs, shift SIG. cD -> fp32 gmem (STG.128
// interior). !LAST: cA -> qn at ext base CN (mirror pads inline).
// LAST: cA -> fp32 gmem cAg.
template<int N, int SIG, int C, int CN, bool LAST>
__device__ __forceinline__ void dwtT(const __half* __restrict__ q,
                                     __half* __restrict__ qn,
                                     float* __restrict__ cD,
                                     float* __restrict__ cAg, const int tid)
{
    constexpr int M    = (N + 7) >> 1;
    constexpr int NB   = (M + SIG + 3) >> 2;
    constexpr int ITER = (NB + NT - 1) / NT;
#pragma unroll
    for (int it = 0; it < ITER; it++) {
        const int T = tid + it * NT;
        if (it == ITER - 1 && (NB % NT) != 0 && T >= NB) continue;

        const int j0 = 4 * T - SIG;
        const int h0 = C + 8 * T - 2 * SIG - 2;   // ≡ 0 (mod 8) by choice of C
        const uint4 u0 = *reinterpret_cast<const uint4*>(q + h0);
        const uint4 u1 = *reinterpret_cast<const uint4*>(q + h0 + 8);

        float w[14];
        {
            const __half2* ha = reinterpret_cast<const __half2*>(&u0);
            const __half2* hb = reinterpret_cast<const __half2*>(&u1);
            float2 t;
            t = __half22float2(ha[1]); w[0]  = t.x; w[1]  = t.y;
            t = __half22float2(ha[2]); w[2]  = t.x; w[3]  = t.y;
            t = __half22float2(ha[3]); w[4]  = t.x; w[5]  = t.y;
            t = __half22float2(hb[0]); w[6]  = t.x; w[7]  = t.y;
            t = __half22float2(hb[1]); w[8]  = t.x; w[9]  = t.y;
            t = __half22float2(hb[2]); w[10] = t.x; w[11] = t.y;
            t = __half22float2(hb[3]); w[12] = t.x; w[13] = t.y;
        }

        float lo[4], hi[4];
#pragma unroll
        for (int m = 0; m < 4; m++) taps8(w + 2 * m, lo[m], hi[m]);

        const bool interior = (j0 >= 0) && (j0 + 4 <= M);
        if (interior) {
            *reinterpret_cast<float4*>(cD + j0) =
                make_float4(hi[0], hi[1], hi[2], hi[3]);
            if (LAST)
                *reinterpret_cast<float4*>(cAg + j0) =
                    make_float4(lo[0], lo[1], lo[2], lo[3]);
        } else {
#pragma unroll
            for (int m = 0; m < 4; m++) {
                const int j = j0 + m;
                if (j >= 0 && j < M) {
                    cD[j] = hi[m];
                    if (LAST) cAg[j] = lo[m];
                }
            }
        }

        if (!LAST) {
            if (interior && j0 > 5 && j0 + 3 < M - 8) {
#pragma unroll
                for (int m = 0; m < 4; m++)
                    qn[CN + 6 + j0 + m] = __float2half_rn(lo[m]);
            } else {
#pragma unroll
                for (int m = 0; m < 4; m++) {
                    const int j = j0 + m;
                    if (j < 0 || j >= M) continue;
                    const __half v = __float2half_rn(lo[m]);
                    qn[CN + 6 + j] = v;                          // interior
                    if (j <= 5)      qn[CN + 5 - j] = v;         // left mirror
                    if (j >= M - 8)  qn[CN + 2 * M + 5 - j] = v; // right mirror
                }
            }
        }
    }
}

// Whole per-row cascade, specialized on RM = row & 3.
template<int RM>
__device__ __forceinline__ void run_row(const float* __restrict__ xr,
                                        float* __restrict__ out,
                                        const int row, const int tid,
                                        __half* __restrict__ IN16,
                                        __half* __restrict__ A16,
                                        __half* __restrict__ B16)
{
    constexpr int S1 = (3 * RM) & 3;   // L1=2051 ≡ 3 (mod 4)
    constexpr int S2 = RM & 3;         // L2=1029 ≡ 1
    constexpr int S3 = (2 * RM) & 3;   // L3,L4,L5 ≡ 2
    constexpr int C1 = ((2 * S1 + 4) & 7) + 6;
    constexpr int C2 = ((2 * S2 + 4) & 7) + 6;
    constexpr int C3 = ((2 * S3 + 4) & 7) + 6;

    // Input stage: ext[i] = IN16[C1+i]; exactly 4 iterations.
    {
        const float4* __restrict__ x4 = reinterpret_cast<const float4*>(xr);
#pragma unroll
        for (int it = 0; it < 4; it++) {
            const int u = tid + it * NT;
            const float4 v = x4[u];
            const __half2 p01 = __floats2half2_rn(v.x, v.y);
            const __half2 p23 = __floats2half2_rn(v.z, v.w);
            if ((((C1 + 6) & 3) == 0)) {      // STS.64 when provably aligned
                uint2 ww;
                ww.x = *reinterpret_cast<const unsigned int*>(&p01);
                ww.y = *reinterpret_cast<const unsigned int*>(&p23);
                *reinterpret_cast<uint2*>(IN16 + C1 + 6 + 4 * u) = ww;
            } else {
                __half2* __restrict__ dst =
                    reinterpret_cast<__half2*>(IN16 + C1 + 6);
                dst[2 * u]     = p01;
                dst[2 * u + 1] = p23;
            }
        }
        if (tid < 6) {
            IN16[C1 + tid] = __float2half_rn(xr[5 - tid]);            // left ext
        } else if (tid < 14) {
            const int t = tid - 6;
            IN16[C1 + L0 + 6 + t] = __float2half_rn(xr[L0 - 1 - t]);  // right ext
        }
    }
    __syncthreads();

    float* __restrict__ d1 = out + O_D1 + (size_t)row * L1;
    float* __restrict__ d2 = out + O_D2 + (size_t)row * L2;
    float* __restrict__ d3 = out + O_D3 + (size_t)row * L3;
    float* __restrict__ d4 = out + O_D4 + (size_t)row * L4;
    float* __restrict__ d5 = out + O_D5 + (size_t)row * L5;
    float* __restrict__ ap = out + O_APPROX + (size_t)row * L5;

    dwtT<L0, S1, C1, C2, false>(IN16, A16, d1, nullptr, tid);  // 4096 -> 2051
    __syncthreads();
    dwtT<L1, S2, C2, C3, false>(A16, B16, d2, nullptr, tid);   // 2051 -> 1029
    __syncthreads();
    dwtT<L2, S3, C3, C3, false>(B16, IN16, d3, nullptr, tid);  // 1029 -> 518
    __syncthreads();
    dwtT<L3, S3, C3, C3, false>(IN16, A16, d4, nullptr, tid);  // 518  -> 262
    __syncthreads();
    dwtT<L4, S3, C3, 0, true>(A16, nullptr, d5, ap, tid);      // 262  -> 134
}

__global__ __launch_bounds__(NT, 7)
void wavelet5_kernel(const float* __restrict__ x, float* __restrict__ out) {
    __shared__ __align__(16) __half IN16[4160];  // lvl1 in / lvl3 out / lvl4 in
    __shared__ __align__(16) __half A16[2112];   // lvl1 out / lvl2 in / lvl4 out / lvl5 in
    __shared__ __align__(16) __half B16[1088];   // lvl2 out / lvl3 in

    const int row = blockIdx.x;
    const int tid = threadIdx.x;
    const float* __restrict__ xr = x + (size_t)row * L0;

    switch (row & 3) {
        case 0: run_row<0>(xr, out, row, tid, IN16, A16, B16); break;
        case 1: run_row<1>(xr, out, row, tid, IN16, A16, B16); break;
        case 2: run_row<2>(xr, out, row, tid, IN16, A16, B16); break;
        default: run_row<3>(xr, out, row, tid, IN16, A16, B16); break;
    }
}

extern "C" void kernel_launch(void* const* d_in, const int* in_sizes, int n_in,
                              void* d_out, int out_size) {
    const float* x = (const float*)d_in[0];
    float* out = (float*)d_out;
    (void)in_sizes; (void)n_in; (void)out_size;
    wavelet5_kernel<<<NROWS, NT>>>(x, out);
}

// round 13
// speedup vs baseline: 1.0611x; 1.0611x over previous
#include <cuda_runtime.h>
#include <cuda_fp16.h>

// 5-level db4 DWT, symmetric extension. fp16 smem cascade (fp32 scalar FMA),
// 4 outputs/thread from 2 conflict-free aligned LDS.128 (R5 hot loop).
// Cascade constants (shifts, smem bases, lengths) specialized on row&3 at
// compile time, but level loops stay RUNTIME-strided (#pragma unroll 1) to
// keep code size I$-resident — separating R12's constant-folding win from
// its unroll-bloat loss.

#define NROWS 4096
#define NT    256

#define L0 4096
#define L1 2051
#define L2 1029
#define L3 518
#define L4 262
#define L5 134

#define O_APPROX 0
#define O_D5 (NROWS * L5)
#define O_D4 (O_D5 + NROWS * L5)
#define O_D3 (O_D4 + NROWS * L4)
#define O_D2 (O_D3 + NROWS * L3)
#define O_D1 (O_D2 + NROWS * L2)

// Reversed filters: y[j] = sum_r RF[r] * ext[2j + r]
#define RLO0  0.23037781330885523f
#define RLO1  0.7148465705525415f
#define RLO2  0.6308807679295904f
#define RLO3 -0.02798376941698385f
#define RLO4 -0.18703481171888114f
#define RLO5  0.030841381835986965f
#define RLO6  0.032883011666982945f
#define RLO7 -0.010597401784997278f

#define RHI0 -0.010597401784997278f
#define RHI1 -0.032883011666982945f
#define RHI2  0.030841381835986965f
#define RHI3  0.18703481171888114f
#define RHI4 -0.02798376941698385f
#define RHI5 -0.6308807679295904f
#define RHI6  0.7148465705525415f
#define RHI7 -0.23037781330885523f

__device__ __forceinline__ void taps8(const float* w, float& l, float& h) {
    l = RLO0 * w[0];
    l = fmaf(RLO1, w[1], l); l = fmaf(RLO2, w[2], l);
    l = fmaf(RLO3, w[3], l); l = fmaf(RLO4, w[4], l);
    l = fmaf(RLO5, w[5], l); l = fmaf(RLO6, w[6], l);
    l = fmaf(RLO7, w[7], l);
    h = RHI0 * w[0];
    h = fmaf(RHI1, w[1], h); h = fmaf(RHI2, w[2], h);
    h = fmaf(RHI3, w[3], h); h = fmaf(RHI4, w[4], h);
    h = fmaf(RHI5, w[5], h); h = fmaf(RHI6, w[6], h);
    h = fmaf(RHI7, w[7], h);
}

// One level, compile-time shapes, runtime strided loop (no unroll).
// q: fp16 ext buffer (ext[i] = q[C+i]), input length N, M=(N+7)/2 outputs,
// shift SIG. cD -> fp32 gmem (STG.128 interior). !LAST: cA -> qn at ext base
// CN (mirror pads inline). LAST: cA -> fp32 gmem cAg.
template<int N, int SIG, int C, int CN, bool LAST>
__device__ __forceinline__ void dwtT(const __half* __restrict__ q,
                                     __half* __restrict__ qn,
                                     float* __restrict__ cD,
                                     float* __restrict__ cAg, const int tid)
{
    constexpr int M  = (N + 7) >> 1;
    constexpr int NB = (M + SIG + 3) >> 2;
#pragma unroll 1
    for (int T = tid; T < NB; T += NT) {
        const int j0 = 4 * T - SIG;
        const int h0 = (C - 2 * SIG - 2) + 8 * T;   // ≡ 0 (mod 8) by choice of C
        const uint4 u0 = *reinterpret_cast<const uint4*>(q + h0);
        const uint4 u1 = *reinterpret_cast<const uint4*>(q + h0 + 8);

        float w[14];
        {
            const __half2* ha = reinterpret_cast<const __half2*>(&u0);
            const __half2* hb = reinterpret_cast<const __half2*>(&u1);
            float2 t;
            t = __half22float2(ha[1]); w[0]  = t.x; w[1]  = t.y;
            t = __half22float2(ha[2]); w[2]  = t.x; w[3]  = t.y;
            t = __half22float2(ha[3]); w[4]  = t.x; w[5]  = t.y;
            t = __half22float2(hb[0]); w[6]  = t.x; w[7]  = t.y;
            t = __half22float2(hb[1]); w[8]  = t.x; w[9]  = t.y;
            t = __half22float2(hb[2]); w[10] = t.x; w[11] = t.y;
            t = __half22float2(hb[3]); w[12] = t.x; w[13] = t.y;
        }

        float lo[4], hi[4];
#pragma unroll
        for (int m = 0; m < 4; m++) taps8(w + 2 * m, lo[m], hi[m]);

        const bool interior = (j0 >= 0) && (j0 + 4 <= M);
        if (interior) {
            *reinterpret_cast<float4*>(cD + j0) =
                make_float4(hi[0], hi[1], hi[2], hi[3]);
            if (LAST)
                *reinterpret_cast<float4*>(cAg + j0) =
                    make_float4(lo[0], lo[1], lo[2], lo[3]);
        } else {
#pragma unroll
            for (int m = 0; m < 4; m++) {
                const int j = j0 + m;
                if (j >= 0 && j < M) {
                    cD[j] = hi[m];
                    if (LAST) cAg[j] = lo[m];
                }
            }
        }

        if (!LAST) {
            if (interior && j0 > 5 && j0 + 3 < M - 8) {
#pragma unroll
                for (int m = 0; m < 4; m++)
                    qn[CN + 6 + j0 + m] = __float2half_rn(lo[m]);
            } else {
#pragma unroll
                for (int m = 0; m < 4; m++) {
                    const int j = j0 + m;
                    if (j < 0 || j >= M) continue;
                    const __half v = __float2half_rn(lo[m]);
                    qn[CN + 6 + j] = v;                          // interior
                    if (j <= 5)      qn[CN + 5 - j] = v;         // left mirror
                    if (j >= M - 8)  qn[CN + 2 * M + 5 - j] = v; // right mirror
                }
            }
        }
    }
}

// Whole per-row cascade, specialized on RM = row & 3.
template<int RM>
__device__ __forceinline__ void run_row(const float* __restrict__ xr,
                                        float* __restrict__ out,
                                        const int row, const int tid,
                                        __half* __restrict__ IN16,
                                        __half* __restrict__ A16,
                                        __half* __restrict__ B16)
{
    constexpr int S1 = (3 * RM) & 3;   // L1=2051 ≡ 3 (mod 4)
    constexpr int S2 = RM & 3;         // L2=1029 ≡ 1
    constexpr int S3 = (2 * RM) & 3;   // L3,L4,L5 ≡ 2
    constexpr int C1 = ((2 * S1 + 4) & 7) + 6;
    constexpr int C2 = ((2 * S2 + 4) & 7) + 6;
    constexpr int C3 = ((2 * S3 + 4) & 7) + 6;

    // Input stage: ext[i] = IN16[C1+i]
    {
        const float4* __restrict__ x4 = reinterpret_cast<const float4*>(xr);
        __half2* __restrict__ dst = reinterpret_cast<__half2*>(IN16 + C1 + 6);
#pragma unroll 4
        for (int u = tid; u < L0 / 4; u += NT) {
            const float4 v = x4[u];
            dst[2 * u]     = __floats2half2_rn(v.x, v.y);
            dst[2 * u + 1] = __floats2half2_rn(v.z, v.w);
        }
        if (tid < 6) {
            IN16[C1 + tid] = __float2half_rn(xr[5 - tid]);            // left ext
        } else if (tid < 14) {
            const int t = tid - 6;
            IN16[C1 + L0 + 6 + t] = __float2half_rn(xr[L0 - 1 - t]);  // right ext
        }
    }
    __syncthreads();

    float* __restrict__ d1 = out + O_D1 + (size_t)row * L1;
    float* __restrict__ d2 = out + O_D2 + (size_t)row * L2;
    float* __restrict__ d3 = out + O_D3 + (size_t)row * L3;
    float* __restrict__ d4 = out + O_D4 + (size_t)row * L4;
    float* __restrict__ d5 = out + O_D5 + (size_t)row * L5;
    float* __restrict__ ap = out + O_APPROX + (size_t)row * L5;

    dwtT<L0, S1, C1, C2, false>(IN16, A16, d1, nullptr, tid);  // 4096 -> 2051
    __syncthreads();
    dwtT<L1, S2, C2, C3, false>(A16, B16, d2, nullptr, tid);   // 2051 -> 1029
    __syncthreads();
    dwtT<L2, S3, C3, C3, false>(B16, IN16, d3, nullptr, tid);  // 1029 -> 518
    __syncthreads();
    dwtT<L3, S3, C3, C3, false>(IN16, A16, d4, nullptr, tid);  // 518  -> 262
    __syncthreads();
    dwtT<L4, S3, C3, 0, true>(A16, nullptr, d5, ap, tid);      // 262  -> 134
}

__global__ __launch_bounds__(NT)
void wavelet5_kernel(const float* __restrict__ x, float* __restrict__ out) {
    __shared__ __align__(16) __half IN16[4160];  // lvl1 in / lvl3 out / lvl4 in
    __shared__ __align__(16) __half A16[2112];   // lvl1 out / lvl2 in / lvl4 out / lvl5 in
    __shared__ __align__(16) __half B16[1088];   // lvl2 out / lvl3 in

    const int row = blockIdx.x;
    const int tid = threadIdx.x;
    const float* __restrict__ xr = x + (size_t)row * L0;

    switch (row & 3) {
        case 0: run_row<0>(xr, out, row, tid, IN16, A16, B16); break;
        case 1: run_row<1>(xr, out, row, tid, IN16, A16, B16); break;
        case 2: run_row<2>(xr, out, row, tid, IN16, A16, B16); break;
        default: run_row<3>(xr, out, row, tid, IN16, A16, B16); break;
    }
}

extern "C" void kernel_launch(void* const* d_in, const int* in_sizes, int n_in,
                              void* d_out, int out_size) {
    const float* x = (const float*)d_in[0];
    float* out = (float*)d_out;
    (void)in_sizes; (void)n_in; (void)out_size;
    wavelet5_kernel<<<NROWS, NT>>>(x, out);
}